// round 11
// baseline (speedup 1.0000x reference)
#include <cuda_runtime.h>

#define BB 64
#define LL 512
#define HH 512
#define NBLK 148

typedef unsigned long long ull;

// Scratch (device globals). g_S4 is fully overwritten every launch (no zeroing
// needed). g_UV/g_LV keep the "zero at exit" invariant.
__device__ __align__(16) float g_S4[8][HH][BB][4]; // per-split packed sums
__device__ __align__(16) float g_UV[HH][BB][2];    // packed {U,V}
__device__ __align__(16) float g_LV[BB][HH];
__device__ __align__(16) float g_usr[HH];

// two-level barrier state
__device__ unsigned g_cnt1[320];          // 10 groups, 128B apart
__device__ unsigned g_cnt2;
__device__ volatile unsigned g_gen;

__device__ __forceinline__ void grid_sync() {
    __syncthreads();
    if (threadIdx.x == 0) {
        unsigned gen = g_gen;
        __threadfence();                                  // release
        unsigned g = blockIdx.x >> 4;                     // 10 groups (last has 4)
        unsigned gs = (g == 9u) ? 4u : 16u;
        if (atomicAdd(&g_cnt1[g * 32], 1u) == gs - 1u) {
            g_cnt1[g * 32] = 0u;
            __threadfence();
            if (atomicAdd(&g_cnt2, 1u) == 9u) {
                g_cnt2 = 0u;
                __threadfence();
                g_gen = gen + 1u;
            } else {
                while (g_gen == gen) {}
            }
        } else {
            while (g_gen == gen) {}
        }
        __threadfence();                                  // acquire
    }
    __syncthreads();
}

// ---- packed fp32x2 helpers -------------------------------------------------
__device__ __forceinline__ ull pack2(float x, float y) {
    ull r; asm("mov.b64 %0, {%1, %2};" : "=l"(r) : "f"(x), "f"(y)); return r;
}
__device__ __forceinline__ ull bcast2(float x) { return pack2(x, x); }
__device__ __forceinline__ float2 unpack2(ull v) {
    float2 r; asm("mov.b64 {%0, %1}, %2;" : "=f"(r.x), "=f"(r.y) : "l"(v)); return r;
}
__device__ __forceinline__ void ffma2(ull& d, ull a, ull b) {
    asm("fma.rn.f32x2 %0, %1, %2, %0;" : "+l"(d) : "l"(a), "l"(b));
}

__global__ void __launch_bounds__(1024, 1) k_fused(
        const float* __restrict__ tdu, const float* __restrict__ tdl,
        const float* __restrict__ ldu, const float* __restrict__ ldl,
        const int*   __restrict__ cur, const int* __restrict__ llen,
        const float* __restrict__ wih, const float* __restrict__ wtu,
        const float* __restrict__ wtl, const float* __restrict__ wsu,
        const float* __restrict__ wsl, const float* __restrict__ h0,
        const float* __restrict__ locw, float* __restrict__ out) {
    __shared__ __align__(16) unsigned char smem_raw[49152];
    const int B = blockIdx.x;
    const int t = threadIdx.x;

    // ============= P1: gather, static assignment, sync-free streaming =======
    // 512 units: u = B*4 + which (B<128). b = u & 63, sp = u >> 6 (8 splits).
    // Unit = 256 threads, thread owns an h-pair. Plain stores -> idempotent.
    // EXECUTED TWICE (probe): second pass rewrites identical values; the dur
    // delta vs a single pass measures P1's true cost.
    {
        __shared__ __align__(16) float4 s_cf[4][64];
        __shared__ int s_idx[4][64];

        if (B >= 140) {   // usr_vec = Wih @ h0 : 8 blocks x 64 k, 16 lanes/k
            int k    = (B - 140) * 64 + (t >> 4);
            int lane = t & 15;
            float s = 0.f;
            #pragma unroll 8
            for (int h = lane; h < HH; h += 16)
                s += wih[(size_t)k * HH + h] * __ldg(&h0[h]);
            #pragma unroll
            for (int o = 8; o; o >>= 1) s += __shfl_down_sync(0xffffffffu, s, o, 16);
            if (lane == 0) g_usr[k] = s;
        }

        if (B < 128) {
            #pragma unroll 1
            for (int rep = 0; rep < 2; ++rep) {
                // stage coefficients: threads 0..255 cover 4 units x 64 rows
                if (t < 256) {
                    int ws = t >> 6, r = t & 63;
                    int u = B * 4 + ws;
                    int b = u & 63, sp = u >> 6;
                    int len = __ldg(&llen[b]);
                    int l = sp + 8 * r;
                    if (l < len) {
                        int o = b * LL + l;
                        float tu = tdu[o], tl = tdl[o];
                        float lu = ldu[o], ll = ldl[o];
                        float tden = 1.f / (tu + tl + 1e-9f);
                        float lden = 1.f / (lu + ll + 1e-9f);
                        float a = tu * tden, bb_ = tl * tden;
                        float c = lu * lden, dd  = ll * lden;
                        s_cf[ws][r]  = make_float4(c * a, c * bb_, dd * a, dd * bb_);
                        s_idx[ws][r] = cur[o];
                    }
                }
                __syncthreads();

                // stream: 4 units x 256 threads; thread owns h-pair at 2*h2
                int which = t >> 8, h2 = t & 255;
                int u = B * 4 + which;
                int b = u & 63, sp = u >> 6;
                int len = __ldg(&llen[b]);
                int cnt = (len > sp) ? ((len - sp + 7) >> 3) : 0;

                const int*    ix  = s_idx[which];
                const float4* cfp = s_cf[which];
                const float*  base = locw + 2 * h2;

                ull a1 = 0, a2 = 0, a3 = 0, a4 = 0;     // packed (h_even, h_odd)
                int r = 0;
                for (; r + 4 <= cnt; r += 4) {
                    ull v0 = __ldg(reinterpret_cast<const ull*>(base + (size_t)ix[r]     * HH));
                    ull v1 = __ldg(reinterpret_cast<const ull*>(base + (size_t)ix[r + 1] * HH));
                    ull v2 = __ldg(reinterpret_cast<const ull*>(base + (size_t)ix[r + 2] * HH));
                    ull v3 = __ldg(reinterpret_cast<const ull*>(base + (size_t)ix[r + 3] * HH));
                    float4 c0 = cfp[r], c1 = cfp[r + 1], c2 = cfp[r + 2], c3 = cfp[r + 3];
                    ffma2(a1, bcast2(c0.x), v0); ffma2(a2, bcast2(c0.y), v0);
                    ffma2(a3, bcast2(c0.z), v0); ffma2(a4, bcast2(c0.w), v0);
                    ffma2(a1, bcast2(c1.x), v1); ffma2(a2, bcast2(c1.y), v1);
                    ffma2(a3, bcast2(c1.z), v1); ffma2(a4, bcast2(c1.w), v1);
                    ffma2(a1, bcast2(c2.x), v2); ffma2(a2, bcast2(c2.y), v2);
                    ffma2(a3, bcast2(c2.z), v2); ffma2(a4, bcast2(c2.w), v2);
                    ffma2(a1, bcast2(c3.x), v3); ffma2(a2, bcast2(c3.y), v3);
                    ffma2(a3, bcast2(c3.z), v3); ffma2(a4, bcast2(c3.w), v3);
                }
                for (; r < cnt; ++r) {
                    ull v = __ldg(reinterpret_cast<const ull*>(base + (size_t)ix[r] * HH));
                    float4 cf = cfp[r];
                    ffma2(a1, bcast2(cf.x), v); ffma2(a2, bcast2(cf.y), v);
                    ffma2(a3, bcast2(cf.z), v); ffma2(a4, bcast2(cf.w), v);
                }
                // unconditional plain stores (zeros when cnt==0) — idempotent
                {
                    float2 e1 = unpack2(a1), e2 = unpack2(a2),
                           e3 = unpack2(a3), e4 = unpack2(a4);
                    *reinterpret_cast<float4*>(&g_S4[sp][2 * h2][b][0]) =
                        make_float4(e1.x, e2.x, e3.x, e4.x);
                    *reinterpret_cast<float4*>(&g_S4[sp][2 * h2 + 1][b][0]) =
                        make_float4(e1.y, e2.y, e3.y, e4.y);
                }
                __syncthreads();   // s_cf reusable for next rep
            }
        }
    }
    grid_sync();

    // ============= P2: mm1  U/V[k][b] = sum_h Wt{u,l}[k][h] * S[h][b] =======
    if (B < 128) {
        int kblk = B >> 4, hsplit = B & 15;        // 8 kblk x 64k, 16 hsplit x 32h
        int k0 = kblk * 64, hb = hsplit * 32;
        float* s_t = reinterpret_cast<float*>(smem_raw);           // [32h][4s][64b]
        float* swt = reinterpret_cast<float*>(smem_raw + 32768);   // [2m][64k][32h]
        #pragma unroll
        for (int i = t; i < 2048; i += 1024) {
            int h = i >> 6, b = i & 63;
            float4 a0 = __ldcg(reinterpret_cast<const float4*>(&g_S4[0][hb + h][b][0]));
            float4 a1 = __ldcg(reinterpret_cast<const float4*>(&g_S4[1][hb + h][b][0]));
            float4 a2 = __ldcg(reinterpret_cast<const float4*>(&g_S4[2][hb + h][b][0]));
            float4 a3 = __ldcg(reinterpret_cast<const float4*>(&g_S4[3][hb + h][b][0]));
            float4 a4 = __ldcg(reinterpret_cast<const float4*>(&g_S4[4][hb + h][b][0]));
            float4 a5 = __ldcg(reinterpret_cast<const float4*>(&g_S4[5][hb + h][b][0]));
            float4 a6 = __ldcg(reinterpret_cast<const float4*>(&g_S4[6][hb + h][b][0]));
            float4 a7 = __ldcg(reinterpret_cast<const float4*>(&g_S4[7][hb + h][b][0]));
            float sx = a0.x + a1.x + a2.x + a3.x + a4.x + a5.x + a6.x + a7.x;
            float sy = a0.y + a1.y + a2.y + a3.y + a4.y + a5.y + a6.y + a7.y;
            float sz = a0.z + a1.z + a2.z + a3.z + a4.z + a5.z + a6.z + a7.z;
            float sw = a0.w + a1.w + a2.w + a3.w + a4.w + a5.w + a6.w + a7.w;
            float* p = &s_t[h * 256 + b];
            p[0] = sx; p[64] = sy; p[128] = sz; p[192] = sw;
        }
        {
            int m = t >> 9, r = (t >> 3) & 63, i4 = t & 7;
            const float* W = m ? wtl : wtu;
            float4 v = __ldg(reinterpret_cast<const float4*>(
                           &W[(size_t)(k0 + r) * HH + hb + i4 * 4]));
            *reinterpret_cast<float4*>(&swt[(m * 64 + r) * 32 + i4 * 4]) = v;
        }
        __syncthreads();
        int w = t >> 5, lane = t & 31;
        int kg = w & 15, hs = w >> 4;              // 16 kgroups x 4k, 2 hsubs x 16h
        int kb = kg * 4;
        ull aU[4] = {0, 0, 0, 0}, aV[4] = {0, 0, 0, 0};   // packed (b0, b0+1)
        for (int hh = 0; hh < 16; ++hh) {
            int h = hs * 16 + hh;
            const float* row = &s_t[h * 256];
            ull s1 = *reinterpret_cast<const ull*>(&row[2 * lane]);
            ull s2 = *reinterpret_cast<const ull*>(&row[64 + 2 * lane]);
            ull s3 = *reinterpret_cast<const ull*>(&row[128 + 2 * lane]);
            ull s4 = *reinterpret_cast<const ull*>(&row[192 + 2 * lane]);
            #pragma unroll
            for (int j = 0; j < 4; ++j) {
                ull wu = bcast2(swt[(kb + j) * 32 + h]);
                ull wl = bcast2(swt[(64 + kb + j) * 32 + h]);
                ffma2(aU[j], wu, s1); ffma2(aU[j], wl, s2);
                ffma2(aV[j], wu, s3); ffma2(aV[j], wl, s4);
            }
        }
        __syncthreads();
        float4* ub = reinterpret_cast<float4*>(smem_raw);   // [64k][32 pairs]
        #pragma unroll
        for (int p = 0; p < 2; ++p) {
            if (hs == p) {
                #pragma unroll
                for (int j = 0; j < 4; ++j) {
                    float2 u = unpack2(aU[j]), v = unpack2(aV[j]);
                    int idx = (kb + j) * 32 + lane;
                    if (p == 0) ub[idx] = make_float4(u.x, v.x, u.y, v.y);
                    else {
                        float4 x = ub[idx];
                        x.x += u.x; x.y += v.x; x.z += u.y; x.w += v.y;
                        ub[idx] = x;
                    }
                }
            }
            __syncthreads();
        }
        float4* dst = reinterpret_cast<float4*>(&g_UV[k0][0][0]);
        atomicAdd(&dst[t],        ub[t]);
        atomicAdd(&dst[t + 1024], ub[t + 1024]);
    }
    grid_sync();

    // ============= P3: mm2  LV[b][k] = sum_h Ws{u,l}[k][h]*{U,V}[h][b] ======
    if (B < 128) {
        int kblk = B >> 3, hsplit = B & 7;         // 16 kblk x 32k, 8 hsplit x 64h
        int k0 = kblk * 32, hb = hsplit * 64;
        ull*   uP  = reinterpret_cast<ull*>(smem_raw);             // [64h][32bp]
        ull*   vP  = reinterpret_cast<ull*>(smem_raw + 16384);     // [64h][32bp]
        float* swt = reinterpret_cast<float*>(smem_raw + 32768);   // [2m][32k][64h]
        #pragma unroll
        for (int i = t; i < 2048; i += 1024) {
            int h = i >> 5, bp = i & 31;
            float4 q = __ldcg(reinterpret_cast<const float4*>(&g_UV[hb + h][bp * 2][0]));
            uP[h * 32 + bp] = pack2(q.x, q.z);     // (U_b0, U_b1)
            vP[h * 32 + bp] = pack2(q.y, q.w);     // (V_b0, V_b1)
        }
        {
            int m = t >> 9, r = (t >> 4) & 31, i4 = t & 15;
            const float* W = m ? wsl : wsu;
            float4 v = __ldg(reinterpret_cast<const float4*>(
                           &W[(size_t)(k0 + r) * HH + hb + i4 * 4]));
            *reinterpret_cast<float4*>(&swt[(m * 32 + r) * 64 + i4 * 4]) = v;
        }
        __syncthreads();
        int w = t >> 5, lane = t & 31;
        int kg = w & 7, hs = w >> 3;               // 8 kgroups x 4k, 4 hsubs x 16h
        int kb = kg * 4;
        ull acc[4] = {0, 0, 0, 0};                 // packed (b0, b0+1)
        for (int hh = 0; hh < 16; ++hh) {
            int h = hs * 16 + hh;
            ull up = uP[h * 32 + lane];
            ull vp = vP[h * 32 + lane];
            #pragma unroll
            for (int j = 0; j < 4; ++j) {
                ull wu = bcast2(swt[(kb + j) * 64 + h]);
                ull wl = bcast2(swt[(32 + kb + j) * 64 + h]);
                ffma2(acc[j], wu, up); ffma2(acc[j], wl, vp);
            }
        }
        __syncthreads();
        float* lv = reinterpret_cast<float*>(smem_raw);   // [32k][64b]
        #pragma unroll
        for (int p = 0; p < 4; ++p) {
            if (hs == p) {
                #pragma unroll
                for (int j = 0; j < 4; ++j) {
                    float2 u = unpack2(acc[j]);
                    int r0 = (kb + j) * 64 + 2 * lane;
                    if (p == 0) { lv[r0] = u.x; lv[r0 + 1] = u.y; }
                    else        { lv[r0] += u.x; lv[r0 + 1] += u.y; }
                }
            }
            __syncthreads();
        }
        int b = t & 63, k = (t >> 6) * 2;
        float2 v = make_float2(lv[k * 64 + b], lv[(k + 1) * 64 + b]);
        atomicAdd(reinterpret_cast<float2*>(&g_LV[b][k0 + k]), v);
    }
    grid_sync();

    // ============= P4: softmax (+ zero g_LV / g_UV for next replay) =========
    if (B < 64) {
        float* red = reinterpret_cast<float*>(smem_raw);
        int warp = t >> 5, lane = t & 31;
        float x = -1e30f;
        if (t < 512) {
            x = __ldcg(&g_LV[B][t]) + __ldcg(&g_usr[t]);
            g_LV[B][t] = 0.f;                      // restore invariant
        }
        float m = x;
        #pragma unroll
        for (int o = 16; o; o >>= 1) m = fmaxf(m, __shfl_xor_sync(0xffffffffu, m, o));
        if (lane == 0) red[warp] = m;
        __syncthreads();
        if (t == 0) {
            float M = red[0];
            #pragma unroll
            for (int i = 1; i < 32; ++i) M = fmaxf(M, red[i]);
            red[32] = M;
        }
        __syncthreads();
        float M = red[32];
        float e = (t < 512) ? expf(x - M) : 0.f;
        float s = e;
        #pragma unroll
        for (int o = 16; o; o >>= 1) s += __shfl_xor_sync(0xffffffffu, s, o);
        __syncthreads();
        if (lane == 0) red[warp] = s;
        __syncthreads();
        if (t == 0) {
            float S = 0.f;
            #pragma unroll
            for (int i = 0; i < 32; ++i) S += red[i];
            red[33] = S;
        }
        __syncthreads();
        if (t < 512) out[B * HH + t] = e * (1.f / red[33]);
    } else {
        // restore g_UV == 0 invariant
        int idx = (B - 64) * 1024 + t;
        if (idx < 16384)
            reinterpret_cast<float4*>(g_UV)[idx] = make_float4(0.f, 0.f, 0.f, 0.f);
    }
}

// ---------------------------------------------------------------------------
extern "C" void kernel_launch(void* const* d_in, const int* in_sizes, int n_in,
                              void* d_out, int out_size) {
    const float* tdu  = (const float*)d_in[0];
    const float* tdl  = (const float*)d_in[1];
    const float* ldu  = (const float*)d_in[2];
    const float* ldl  = (const float*)d_in[3];
    const int*   cur  = (const int*)  d_in[4];
    const int*   llen = (const int*)  d_in[5];
    const float* wih  = (const float*)d_in[6];
    const float* wtu  = (const float*)d_in[7];
    const float* wtl  = (const float*)d_in[8];
    const float* wsu  = (const float*)d_in[9];
    const float* wsl  = (const float*)d_in[10];
    const float* h0   = (const float*)d_in[11];
    const float* locw = (const float*)d_in[12];
    float* out = (float*)d_out;

    k_fused<<<NBLK, 1024>>>(tdu, tdl, ldu, ldl, cur, llen,
                            wih, wtu, wtl, wsu, wsl, h0, locw, out);
}

// round 12
// speedup vs baseline: 1.2205x; 1.2205x over previous
#include <cuda_runtime.h>

#define BB 64
#define LL 512
#define HH 512
#define NBLK 148

typedef unsigned long long ull;

// Scratch (device globals). g_S4 and g_LV8 are fully overwritten every launch
// (no zeroing needed). g_UV keeps the "zero at exit" invariant.
__device__ __align__(16) float g_S4[8][HH][BB][4]; // per-split packed sums
__device__ __align__(16) float g_UV[HH][BB][2];    // packed {U,V}
__device__ __align__(16) float g_LV8[8][BB][HH];   // per-hsplit loc_vec partials
__device__ __align__(16) float g_usr[HH];

// two-level barrier state
__device__ unsigned g_cnt1[320];          // 10 groups, 128B apart
__device__ unsigned g_cnt2;
__device__ volatile unsigned g_gen;

__device__ __forceinline__ void grid_sync() {
    __syncthreads();
    if (threadIdx.x == 0) {
        unsigned gen = g_gen;
        __threadfence();                                  // release
        unsigned g = blockIdx.x >> 4;                     // 10 groups (last has 4)
        unsigned gs = (g == 9u) ? 4u : 16u;
        if (atomicAdd(&g_cnt1[g * 32], 1u) == gs - 1u) {
            g_cnt1[g * 32] = 0u;
            __threadfence();
            if (atomicAdd(&g_cnt2, 1u) == 9u) {
                g_cnt2 = 0u;
                __threadfence();
                g_gen = gen + 1u;
            } else {
                while (g_gen == gen) {}
            }
        } else {
            while (g_gen == gen) {}
        }
        __threadfence();                                  // acquire
    }
    __syncthreads();
}

// ---- packed fp32x2 helpers -------------------------------------------------
__device__ __forceinline__ ull pack2(float x, float y) {
    ull r; asm("mov.b64 %0, {%1, %2};" : "=l"(r) : "f"(x), "f"(y)); return r;
}
__device__ __forceinline__ ull bcast2(float x) { return pack2(x, x); }
__device__ __forceinline__ float2 unpack2(ull v) {
    float2 r; asm("mov.b64 {%0, %1}, %2;" : "=f"(r.x), "=f"(r.y) : "l"(v)); return r;
}
__device__ __forceinline__ void ffma2(ull& d, ull a, ull b) {
    asm("fma.rn.f32x2 %0, %1, %2, %0;" : "+l"(d) : "l"(a), "l"(b));
}

__global__ void __launch_bounds__(1024, 1) k_fused(
        const float* __restrict__ tdu, const float* __restrict__ tdl,
        const float* __restrict__ ldu, const float* __restrict__ ldl,
        const int*   __restrict__ cur, const int* __restrict__ llen,
        const float* __restrict__ wih, const float* __restrict__ wtu,
        const float* __restrict__ wtl, const float* __restrict__ wsu,
        const float* __restrict__ wsl, const float* __restrict__ h0,
        const float* __restrict__ locw, float* __restrict__ out) {
    __shared__ __align__(16) unsigned char smem_raw[49152];
    const int B = blockIdx.x;
    const int t = threadIdx.x;

    // ============= P1: gather, static assignment, sync-free streaming =======
    // 512 units: u = B*4 + which (B<128). b = u & 63, sp = u >> 6 (8 splits).
    // Unit = 256 threads, thread owns an h-pair. Plain stores (idempotent).
    {
        __shared__ __align__(16) float4 s_cf[4][64];
        __shared__ int s_idx[4][64];

        if (B >= 140) {   // usr_vec = Wih @ h0 : 8 blocks x 64 k, 16 lanes/k
            int k    = (B - 140) * 64 + (t >> 4);
            int lane = t & 15;
            float s = 0.f;
            #pragma unroll 8
            for (int h = lane; h < HH; h += 16)
                s += wih[(size_t)k * HH + h] * __ldg(&h0[h]);
            #pragma unroll
            for (int o = 8; o; o >>= 1) s += __shfl_down_sync(0xffffffffu, s, o, 16);
            if (lane == 0) g_usr[k] = s;
        }

        if (B < 128) {
            // stage coefficients: threads 0..255 cover 4 units x 64 rows
            if (t < 256) {
                int ws = t >> 6, r = t & 63;
                int u = B * 4 + ws;
                int b = u & 63, sp = u >> 6;
                int len = __ldg(&llen[b]);
                int l = sp + 8 * r;
                if (l < len) {
                    int o = b * LL + l;
                    float tu = tdu[o], tl = tdl[o];
                    float lu = ldu[o], ll = ldl[o];
                    float tden = 1.f / (tu + tl + 1e-9f);
                    float lden = 1.f / (lu + ll + 1e-9f);
                    float a = tu * tden, bb_ = tl * tden;
                    float c = lu * lden, dd  = ll * lden;
                    s_cf[ws][r]  = make_float4(c * a, c * bb_, dd * a, dd * bb_);
                    s_idx[ws][r] = cur[o];
                }
            }
            __syncthreads();

            // stream: 4 units x 256 threads; thread owns h-pair at 2*h2
            int which = t >> 8, h2 = t & 255;
            int u = B * 4 + which;
            int b = u & 63, sp = u >> 6;
            int len = __ldg(&llen[b]);
            int cnt = (len > sp) ? ((len - sp + 7) >> 3) : 0;

            const int*    ix  = s_idx[which];
            const float4* cfp = s_cf[which];
            const float*  base = locw + 2 * h2;

            ull a1 = 0, a2 = 0, a3 = 0, a4 = 0;     // packed (h_even, h_odd)
            int r = 0;
            for (; r + 4 <= cnt; r += 4) {
                ull v0 = __ldg(reinterpret_cast<const ull*>(base + (size_t)ix[r]     * HH));
                ull v1 = __ldg(reinterpret_cast<const ull*>(base + (size_t)ix[r + 1] * HH));
                ull v2 = __ldg(reinterpret_cast<const ull*>(base + (size_t)ix[r + 2] * HH));
                ull v3 = __ldg(reinterpret_cast<const ull*>(base + (size_t)ix[r + 3] * HH));
                float4 c0 = cfp[r], c1 = cfp[r + 1], c2 = cfp[r + 2], c3 = cfp[r + 3];
                ffma2(a1, bcast2(c0.x), v0); ffma2(a2, bcast2(c0.y), v0);
                ffma2(a3, bcast2(c0.z), v0); ffma2(a4, bcast2(c0.w), v0);
                ffma2(a1, bcast2(c1.x), v1); ffma2(a2, bcast2(c1.y), v1);
                ffma2(a3, bcast2(c1.z), v1); ffma2(a4, bcast2(c1.w), v1);
                ffma2(a1, bcast2(c2.x), v2); ffma2(a2, bcast2(c2.y), v2);
                ffma2(a3, bcast2(c2.z), v2); ffma2(a4, bcast2(c2.w), v2);
                ffma2(a1, bcast2(c3.x), v3); ffma2(a2, bcast2(c3.y), v3);
                ffma2(a3, bcast2(c3.z), v3); ffma2(a4, bcast2(c3.w), v3);
            }
            for (; r < cnt; ++r) {
                ull v = __ldg(reinterpret_cast<const ull*>(base + (size_t)ix[r] * HH));
                float4 cf = cfp[r];
                ffma2(a1, bcast2(cf.x), v); ffma2(a2, bcast2(cf.y), v);
                ffma2(a3, bcast2(cf.z), v); ffma2(a4, bcast2(cf.w), v);
            }
            // unconditional plain stores (zeros when cnt==0)
            {
                float2 e1 = unpack2(a1), e2 = unpack2(a2),
                       e3 = unpack2(a3), e4 = unpack2(a4);
                *reinterpret_cast<float4*>(&g_S4[sp][2 * h2][b][0]) =
                    make_float4(e1.x, e2.x, e3.x, e4.x);
                *reinterpret_cast<float4*>(&g_S4[sp][2 * h2 + 1][b][0]) =
                    make_float4(e1.y, e2.y, e3.y, e4.y);
            }
        }
    }
    grid_sync();

    // ============= P2: mm1  U/V[k][b] = sum_h Wt{u,l}[k][h] * S[h][b] =======
    if (B < 128) {
        int kblk = B >> 4, hsplit = B & 15;        // 8 kblk x 64k, 16 hsplit x 32h
        int k0 = kblk * 64, hb = hsplit * 32;
        float* s_t = reinterpret_cast<float*>(smem_raw);           // [32h][4s][64b]
        float* swt = reinterpret_cast<float*>(smem_raw + 32768);   // [2m][64k][32h]
        #pragma unroll
        for (int i = t; i < 2048; i += 1024) {
            int h = i >> 6, b = i & 63;
            float4 a0 = __ldcg(reinterpret_cast<const float4*>(&g_S4[0][hb + h][b][0]));
            float4 a1 = __ldcg(reinterpret_cast<const float4*>(&g_S4[1][hb + h][b][0]));
            float4 a2 = __ldcg(reinterpret_cast<const float4*>(&g_S4[2][hb + h][b][0]));
            float4 a3 = __ldcg(reinterpret_cast<const float4*>(&g_S4[3][hb + h][b][0]));
            float4 a4 = __ldcg(reinterpret_cast<const float4*>(&g_S4[4][hb + h][b][0]));
            float4 a5 = __ldcg(reinterpret_cast<const float4*>(&g_S4[5][hb + h][b][0]));
            float4 a6 = __ldcg(reinterpret_cast<const float4*>(&g_S4[6][hb + h][b][0]));
            float4 a7 = __ldcg(reinterpret_cast<const float4*>(&g_S4[7][hb + h][b][0]));
            float sx = a0.x + a1.x + a2.x + a3.x + a4.x + a5.x + a6.x + a7.x;
            float sy = a0.y + a1.y + a2.y + a3.y + a4.y + a5.y + a6.y + a7.y;
            float sz = a0.z + a1.z + a2.z + a3.z + a4.z + a5.z + a6.z + a7.z;
            float sw = a0.w + a1.w + a2.w + a3.w + a4.w + a5.w + a6.w + a7.w;
            float* p = &s_t[h * 256 + b];
            p[0] = sx; p[64] = sy; p[128] = sz; p[192] = sw;
        }
        {
            int m = t >> 9, r = (t >> 3) & 63, i4 = t & 7;
            const float* W = m ? wtl : wtu;
            float4 v = __ldg(reinterpret_cast<const float4*>(
                           &W[(size_t)(k0 + r) * HH + hb + i4 * 4]));
            *reinterpret_cast<float4*>(&swt[(m * 64 + r) * 32 + i4 * 4]) = v;
        }
        __syncthreads();
        int w = t >> 5, lane = t & 31;
        int kg = w & 15, hs = w >> 4;              // 16 kgroups x 4k, 2 hsubs x 16h
        int kb = kg * 4;
        ull aU[4] = {0, 0, 0, 0}, aV[4] = {0, 0, 0, 0};   // packed (b0, b0+1)
        #pragma unroll 1
        for (int hq = 0; hq < 8; ++hq) {           // 2 h per iteration
            int h = hs * 16 + hq * 2;
            // weight broadcasts batched over the h-pair (LDS.64, lane-uniform)
            ull wu2[4], wl2[4];
            #pragma unroll
            for (int j = 0; j < 4; ++j) {
                wu2[j] = *reinterpret_cast<const ull*>(&swt[(kb + j) * 32 + h]);
                wl2[j] = *reinterpret_cast<const ull*>(&swt[(64 + kb + j) * 32 + h]);
            }
            #pragma unroll
            for (int d = 0; d < 2; ++d) {
                const float* row = &s_t[(h + d) * 256];
                ull s1 = *reinterpret_cast<const ull*>(&row[2 * lane]);
                ull s2 = *reinterpret_cast<const ull*>(&row[64 + 2 * lane]);
                ull s3 = *reinterpret_cast<const ull*>(&row[128 + 2 * lane]);
                ull s4 = *reinterpret_cast<const ull*>(&row[192 + 2 * lane]);
                #pragma unroll
                for (int j = 0; j < 4; ++j) {
                    float2 qu = unpack2(wu2[j]), ql = unpack2(wl2[j]);
                    float wuf = d ? qu.y : qu.x;
                    float wlf = d ? ql.y : ql.x;
                    ull wu = bcast2(wuf), wl = bcast2(wlf);
                    ffma2(aU[j], wu, s1); ffma2(aU[j], wl, s2);
                    ffma2(aV[j], wu, s3); ffma2(aV[j], wl, s4);
                }
            }
        }
        __syncthreads();
        float4* ub = reinterpret_cast<float4*>(smem_raw);   // [64k][32 pairs]
        #pragma unroll
        for (int p = 0; p < 2; ++p) {
            if (hs == p) {
                #pragma unroll
                for (int j = 0; j < 4; ++j) {
                    float2 u = unpack2(aU[j]), v = unpack2(aV[j]);
                    int idx = (kb + j) * 32 + lane;
                    if (p == 0) ub[idx] = make_float4(u.x, v.x, u.y, v.y);
                    else {
                        float4 x = ub[idx];
                        x.x += u.x; x.y += v.x; x.z += u.y; x.w += v.y;
                        ub[idx] = x;
                    }
                }
            }
            __syncthreads();
        }
        float4* dst = reinterpret_cast<float4*>(&g_UV[k0][0][0]);
        atomicAdd(&dst[t],        ub[t]);
        atomicAdd(&dst[t + 1024], ub[t + 1024]);
    }
    grid_sync();

    // ============= P3: mm2  LV8[hsplit][b][k] = partial over this h-range ===
    if (B < 128) {
        int kblk = B >> 3, hsplit = B & 7;         // 16 kblk x 32k, 8 hsplit x 64h
        int k0 = kblk * 32, hb = hsplit * 64;
        ull*   uP  = reinterpret_cast<ull*>(smem_raw);             // [64h][32bp]
        ull*   vP  = reinterpret_cast<ull*>(smem_raw + 16384);     // [64h][32bp]
        float* swt = reinterpret_cast<float*>(smem_raw + 32768);   // [2m][32k][64h]
        #pragma unroll
        for (int i = t; i < 2048; i += 1024) {
            int h = i >> 5, bp = i & 31;
            float4 q = __ldcg(reinterpret_cast<const float4*>(&g_UV[hb + h][bp * 2][0]));
            uP[h * 32 + bp] = pack2(q.x, q.z);     // (U_b0, U_b1)
            vP[h * 32 + bp] = pack2(q.y, q.w);     // (V_b0, V_b1)
        }
        {
            int m = t >> 9, r = (t >> 4) & 31, i4 = t & 15;
            const float* W = m ? wsl : wsu;
            float4 v = __ldg(reinterpret_cast<const float4*>(
                           &W[(size_t)(k0 + r) * HH + hb + i4 * 4]));
            *reinterpret_cast<float4*>(&swt[(m * 32 + r) * 64 + i4 * 4]) = v;
        }
        __syncthreads();
        int w = t >> 5, lane = t & 31;
        int kg = w & 7, hs = w >> 3;               // 8 kgroups x 4k, 4 hsubs x 16h
        int kb = kg * 4;
        ull acc[4] = {0, 0, 0, 0};                 // packed (b0, b0+1)
        #pragma unroll 1
        for (int hq = 0; hq < 8; ++hq) {           // 2 h per iteration
            int h = hs * 16 + hq * 2;
            ull wu2[4], wl2[4];
            #pragma unroll
            for (int j = 0; j < 4; ++j) {
                wu2[j] = *reinterpret_cast<const ull*>(&swt[(kb + j) * 64 + h]);
                wl2[j] = *reinterpret_cast<const ull*>(&swt[(32 + kb + j) * 64 + h]);
            }
            #pragma unroll
            for (int d = 0; d < 2; ++d) {
                ull up = uP[(h + d) * 32 + lane];
                ull vp = vP[(h + d) * 32 + lane];
                #pragma unroll
                for (int j = 0; j < 4; ++j) {
                    float2 qu = unpack2(wu2[j]), ql = unpack2(wl2[j]);
                    float wuf = d ? qu.y : qu.x;
                    float wlf = d ? ql.y : ql.x;
                    ffma2(acc[j], bcast2(wuf), up);
                    ffma2(acc[j], bcast2(wlf), vp);
                }
            }
        }
        __syncthreads();
        float* lv = reinterpret_cast<float*>(smem_raw);   // [32k][64b]
        #pragma unroll
        for (int p = 0; p < 4; ++p) {
            if (hs == p) {
                #pragma unroll
                for (int j = 0; j < 4; ++j) {
                    float2 u = unpack2(acc[j]);
                    int r0 = (kb + j) * 64 + 2 * lane;
                    if (p == 0) { lv[r0] = u.x; lv[r0 + 1] = u.y; }
                    else        { lv[r0] += u.x; lv[r0 + 1] += u.y; }
                }
            }
            __syncthreads();
        }
        // plain per-hsplit stores — every (hsplit, b, k) written unconditionally
        int b = t & 63, k = (t >> 6) * 2;
        float2 v = make_float2(lv[k * 64 + b], lv[(k + 1) * 64 + b]);
        *reinterpret_cast<float2*>(&g_LV8[hsplit][b][k0 + k]) = v;
    }
    grid_sync();

    // ============= P4: softmax over sum of 8 LV partials ====================
    if (B < 64) {
        float* red = reinterpret_cast<float*>(smem_raw);
        int warp = t >> 5, lane = t & 31;
        float x = -1e30f;
        if (t < 512) {
            float s = __ldcg(&g_LV8[0][B][t]) + __ldcg(&g_LV8[1][B][t])
                    + __ldcg(&g_LV8[2][B][t]) + __ldcg(&g_LV8[3][B][t])
                    + __ldcg(&g_LV8[4][B][t]) + __ldcg(&g_LV8[5][B][t])
                    + __ldcg(&g_LV8[6][B][t]) + __ldcg(&g_LV8[7][B][t]);
            x = s + __ldcg(&g_usr[t]);
        }
        float m = x;
        #pragma unroll
        for (int o = 16; o; o >>= 1) m = fmaxf(m, __shfl_xor_sync(0xffffffffu, m, o));
        if (lane == 0) red[warp] = m;
        __syncthreads();
        if (t == 0) {
            float M = red[0];
            #pragma unroll
            for (int i = 1; i < 32; ++i) M = fmaxf(M, red[i]);
            red[32] = M;
        }
        __syncthreads();
        float M = red[32];
        float e = (t < 512) ? expf(x - M) : 0.f;
        float s = e;
        #pragma unroll
        for (int o = 16; o; o >>= 1) s += __shfl_xor_sync(0xffffffffu, s, o);
        __syncthreads();
        if (lane == 0) red[warp] = s;
        __syncthreads();
        if (t == 0) {
            float S = 0.f;
            #pragma unroll
            for (int i = 0; i < 32; ++i) S += red[i];
            red[33] = S;
        }
        __syncthreads();
        if (t < 512) out[B * HH + t] = e * (1.f / red[33]);
    } else {
        // restore g_UV == 0 invariant
        int idx = (B - 64) * 1024 + t;
        if (idx < 16384)
            reinterpret_cast<float4*>(g_UV)[idx] = make_float4(0.f, 0.f, 0.f, 0.f);
    }
}

// ---------------------------------------------------------------------------
extern "C" void kernel_launch(void* const* d_in, const int* in_sizes, int n_in,
                              void* d_out, int out_size) {
    const float* tdu  = (const float*)d_in[0];
    const float* tdl  = (const float*)d_in[1];
    const float* ldu  = (const float*)d_in[2];
    const float* ldl  = (const float*)d_in[3];
    const int*   cur  = (const int*)  d_in[4];
    const int*   llen = (const int*)  d_in[5];
    const float* wih  = (const float*)d_in[6];
    const float* wtu  = (const float*)d_in[7];
    const float* wtl  = (const float*)d_in[8];
    const float* wsu  = (const float*)d_in[9];
    const float* wsl  = (const float*)d_in[10];
    const float* h0   = (const float*)d_in[11];
    const float* locw = (const float*)d_in[12];
    float* out = (float*)d_out;

    k_fused<<<NBLK, 1024>>>(tdu, tdl, ldu, ldl, cur, llen,
                            wih, wtu, wtl, wsu, wsl, h0, locw, out);
}

// round 15
// speedup vs baseline: 1.2241x; 1.0030x over previous
#include <cuda_runtime.h>

#define BB 64
#define LL 512
#define HH 512
#define NBLK 148

typedef unsigned long long ull;

// Scratch (device globals). g_S4 and g_LV8 are fully overwritten every launch
// (no zeroing needed). g_UV keeps the "zero at exit" invariant.
__device__ __align__(16) float g_S4[8][HH][BB][4]; // per-split packed sums
__device__ __align__(16) float g_UV[HH][BB][2];    // packed {U,V}
__device__ __align__(16) float g_LV8[8][BB][HH];   // per-hsplit loc_vec partials
__device__ __align__(16) float g_usr[HH];

// two-level barrier state
__device__ unsigned g_cnt1[320];          // 10 groups, 128B apart
__device__ unsigned g_cnt2;
__device__ volatile unsigned g_gen;

__device__ __forceinline__ void grid_sync() {
    __syncthreads();
    if (threadIdx.x == 0) {
        unsigned gen = g_gen;
        __threadfence();                                  // release
        unsigned g = blockIdx.x >> 4;                     // 10 groups (last has 4)
        unsigned gs = (g == 9u) ? 4u : 16u;
        if (atomicAdd(&g_cnt1[g * 32], 1u) == gs - 1u) {
            g_cnt1[g * 32] = 0u;
            __threadfence();
            if (atomicAdd(&g_cnt2, 1u) == 9u) {
                g_cnt2 = 0u;
                __threadfence();
                g_gen = gen + 1u;
            } else {
                while (g_gen == gen) {}
            }
        } else {
            while (g_gen == gen) {}
        }
        __threadfence();                                  // acquire
    }
    __syncthreads();
}

// ---- packed fp32x2 helpers -------------------------------------------------
__device__ __forceinline__ ull pack2(float x, float y) {
    ull r; asm("mov.b64 %0, {%1, %2};" : "=l"(r) : "f"(x), "f"(y)); return r;
}
__device__ __forceinline__ ull bcast2(float x) { return pack2(x, x); }
__device__ __forceinline__ float2 unpack2(ull v) {
    float2 r; asm("mov.b64 {%0, %1}, %2;" : "=f"(r.x), "=f"(r.y) : "l"(v)); return r;
}
__device__ __forceinline__ void ffma2(ull& d, ull a, ull b) {
    asm("fma.rn.f32x2 %0, %1, %2, %0;" : "+l"(d) : "l"(a), "l"(b));
}

// ---- L2 evict_last via cache-hint policy: pin reused data in L2 ------------
__device__ __forceinline__ ull l2_policy_el() {
    ull p;
    asm("createpolicy.fractional.L2::evict_last.b64 %0, 1.0;" : "=l"(p));
    return p;
}
__device__ __forceinline__ ull ldg_el64(const float* p, ull pol) {
    ull v;
    asm("ld.global.L2::cache_hint.b64 %0, [%1], %2;"
        : "=l"(v) : "l"(p), "l"(pol));
    return v;
}
__device__ __forceinline__ float4 ldg_el128(const float* p, ull pol) {
    float4 v;
    asm("ld.global.L2::cache_hint.v4.f32 {%0, %1, %2, %3}, [%4], %5;"
        : "=f"(v.x), "=f"(v.y), "=f"(v.z), "=f"(v.w) : "l"(p), "l"(pol));
    return v;
}

__global__ void __launch_bounds__(1024, 1) k_fused(
        const float* __restrict__ tdu, const float* __restrict__ tdl,
        const float* __restrict__ ldu, const float* __restrict__ ldl,
        const int*   __restrict__ cur, const int* __restrict__ llen,
        const float* __restrict__ wih, const float* __restrict__ wtu,
        const float* __restrict__ wtl, const float* __restrict__ wsu,
        const float* __restrict__ wsl, const float* __restrict__ h0,
        const float* __restrict__ locw, float* __restrict__ out) {
    __shared__ __align__(16) unsigned char smem_raw[49152];
    const int B = blockIdx.x;
    const int t = threadIdx.x;
    const ull POL = l2_policy_el();

    // ============= P1: gather, static assignment, sync-free streaming =======
    // 512 units: u = B*4 + which (B<128). b = u & 63, sp = u >> 6 (8 splits).
    // Unit = 256 threads, thread owns an h-pair. Plain stores (idempotent).
    {
        __shared__ __align__(16) float4 s_cf[4][64];
        __shared__ int s_idx[4][64];

        if (B >= 140) {   // usr_vec = Wih @ h0 : 8 blocks x 64 k, 16 lanes/k
            int k    = (B - 140) * 64 + (t >> 4);
            int lane = t & 15;
            float s = 0.f;
            #pragma unroll 8
            for (int h = lane; h < HH; h += 16)
                s += wih[(size_t)k * HH + h] * __ldg(&h0[h]);
            #pragma unroll
            for (int o = 8; o; o >>= 1) s += __shfl_down_sync(0xffffffffu, s, o, 16);
            if (lane == 0) g_usr[k] = s;
        }

        if (B < 128) {
            // stage coefficients: threads 0..255 cover 4 units x 64 rows
            if (t < 256) {
                int ws = t >> 6, r = t & 63;
                int u = B * 4 + ws;
                int b = u & 63, sp = u >> 6;
                int len = __ldg(&llen[b]);
                int l = sp + 8 * r;
                if (l < len) {
                    int o = b * LL + l;
                    float tu = tdu[o], tl = tdl[o];
                    float lu = ldu[o], ll = ldl[o];
                    float tden = 1.f / (tu + tl + 1e-9f);
                    float lden = 1.f / (lu + ll + 1e-9f);
                    float a = tu * tden, bb_ = tl * tden;
                    float c = lu * lden, dd  = ll * lden;
                    s_cf[ws][r]  = make_float4(c * a, c * bb_, dd * a, dd * bb_);
                    s_idx[ws][r] = cur[o];
                }
            }
            __syncthreads();

            // stream: 4 units x 256 threads; thread owns h-pair at 2*h2
            int which = t >> 8, h2 = t & 255;
            int u = B * 4 + which;
            int b = u & 63, sp = u >> 6;
            int len = __ldg(&llen[b]);
            int cnt = (len > sp) ? ((len - sp + 7) >> 3) : 0;

            const int*    ix  = s_idx[which];
            const float4* cfp = s_cf[which];
            const float*  base = locw + 2 * h2;

            ull a1 = 0, a2 = 0, a3 = 0, a4 = 0;     // packed (h_even, h_odd)
            int r = 0;
            for (; r + 4 <= cnt; r += 4) {
                ull v0 = ldg_el64(base + (size_t)ix[r]     * HH, POL);
                ull v1 = ldg_el64(base + (size_t)ix[r + 1] * HH, POL);
                ull v2 = ldg_el64(base + (size_t)ix[r + 2] * HH, POL);
                ull v3 = ldg_el64(base + (size_t)ix[r + 3] * HH, POL);
                float4 c0 = cfp[r], c1 = cfp[r + 1], c2 = cfp[r + 2], c3 = cfp[r + 3];
                ffma2(a1, bcast2(c0.x), v0); ffma2(a2, bcast2(c0.y), v0);
                ffma2(a3, bcast2(c0.z), v0); ffma2(a4, bcast2(c0.w), v0);
                ffma2(a1, bcast2(c1.x), v1); ffma2(a2, bcast2(c1.y), v1);
                ffma2(a3, bcast2(c1.z), v1); ffma2(a4, bcast2(c1.w), v1);
                ffma2(a1, bcast2(c2.x), v2); ffma2(a2, bcast2(c2.y), v2);
                ffma2(a3, bcast2(c2.z), v2); ffma2(a4, bcast2(c2.w), v2);
                ffma2(a1, bcast2(c3.x), v3); ffma2(a2, bcast2(c3.y), v3);
                ffma2(a3, bcast2(c3.z), v3); ffma2(a4, bcast2(c3.w), v3);
            }
            for (; r < cnt; ++r) {
                ull v = ldg_el64(base + (size_t)ix[r] * HH, POL);
                float4 cf = cfp[r];
                ffma2(a1, bcast2(cf.x), v); ffma2(a2, bcast2(cf.y), v);
                ffma2(a3, bcast2(cf.z), v); ffma2(a4, bcast2(cf.w), v);
            }
            // unconditional plain stores (zeros when cnt==0)
            {
                float2 e1 = unpack2(a1), e2 = unpack2(a2),
                       e3 = unpack2(a3), e4 = unpack2(a4);
                *reinterpret_cast<float4*>(&g_S4[sp][2 * h2][b][0]) =
                    make_float4(e1.x, e2.x, e3.x, e4.x);
                *reinterpret_cast<float4*>(&g_S4[sp][2 * h2 + 1][b][0]) =
                    make_float4(e1.y, e2.y, e3.y, e4.y);
            }
        }
    }
    grid_sync();

    // ============= P2: mm1  U/V[k][b] = sum_h Wt{u,l}[k][h] * S[h][b] =======
    if (B < 128) {
        int kblk = B >> 4, hsplit = B & 15;        // 8 kblk x 64k, 16 hsplit x 32h
        int k0 = kblk * 64, hb = hsplit * 32;
        float* s_t = reinterpret_cast<float*>(smem_raw);           // [32h][4s][64b]
        float* swt = reinterpret_cast<float*>(smem_raw + 32768);   // [2m][64k][32h]
        #pragma unroll
        for (int i = t; i < 2048; i += 1024) {
            int h = i >> 6, b = i & 63;
            float4 a0 = __ldcg(reinterpret_cast<const float4*>(&g_S4[0][hb + h][b][0]));
            float4 a1 = __ldcg(reinterpret_cast<const float4*>(&g_S4[1][hb + h][b][0]));
            float4 a2 = __ldcg(reinterpret_cast<const float4*>(&g_S4[2][hb + h][b][0]));
            float4 a3 = __ldcg(reinterpret_cast<const float4*>(&g_S4[3][hb + h][b][0]));
            float4 a4 = __ldcg(reinterpret_cast<const float4*>(&g_S4[4][hb + h][b][0]));
            float4 a5 = __ldcg(reinterpret_cast<const float4*>(&g_S4[5][hb + h][b][0]));
            float4 a6 = __ldcg(reinterpret_cast<const float4*>(&g_S4[6][hb + h][b][0]));
            float4 a7 = __ldcg(reinterpret_cast<const float4*>(&g_S4[7][hb + h][b][0]));
            float sx = a0.x + a1.x + a2.x + a3.x + a4.x + a5.x + a6.x + a7.x;
            float sy = a0.y + a1.y + a2.y + a3.y + a4.y + a5.y + a6.y + a7.y;
            float sz = a0.z + a1.z + a2.z + a3.z + a4.z + a5.z + a6.z + a7.z;
            float sw = a0.w + a1.w + a2.w + a3.w + a4.w + a5.w + a6.w + a7.w;
            float* p = &s_t[h * 256 + b];
            p[0] = sx; p[64] = sy; p[128] = sz; p[192] = sw;
        }
        {
            int m = t >> 9, r = (t >> 3) & 63, i4 = t & 7;
            const float* W = m ? wtl : wtu;
            float4 v = ldg_el128(&W[(size_t)(k0 + r) * HH + hb + i4 * 4], POL);
            *reinterpret_cast<float4*>(&swt[(m * 64 + r) * 32 + i4 * 4]) = v;
        }
        __syncthreads();
        int w = t >> 5, lane = t & 31;
        int kg = w & 15, hs = w >> 4;              // 16 kgroups x 4k, 2 hsubs x 16h
        int kb = kg * 4;
        ull aU[4] = {0, 0, 0, 0}, aV[4] = {0, 0, 0, 0};   // packed (b0, b0+1)
        #pragma unroll 1
        for (int hq = 0; hq < 8; ++hq) {           // 2 h per iteration
            int h = hs * 16 + hq * 2;
            // weight broadcasts batched over the h-pair (LDS.64, lane-uniform)
            ull wu2[4], wl2[4];
            #pragma unroll
            for (int j = 0; j < 4; ++j) {
                wu2[j] = *reinterpret_cast<const ull*>(&swt[(kb + j) * 32 + h]);
                wl2[j] = *reinterpret_cast<const ull*>(&swt[(64 + kb + j) * 32 + h]);
            }
            #pragma unroll
            for (int d = 0; d < 2; ++d) {
                const float* row = &s_t[(h + d) * 256];
                ull s1 = *reinterpret_cast<const ull*>(&row[2 * lane]);
                ull s2 = *reinterpret_cast<const ull*>(&row[64 + 2 * lane]);
                ull s3 = *reinterpret_cast<const ull*>(&row[128 + 2 * lane]);
                ull s4 = *reinterpret_cast<const ull*>(&row[192 + 2 * lane]);
                #pragma unroll
                for (int j = 0; j < 4; ++j) {
                    float2 qu = unpack2(wu2[j]), ql = unpack2(wl2[j]);
                    float wuf = d ? qu.y : qu.x;
                    float wlf = d ? ql.y : ql.x;
                    ull wu = bcast2(wuf), wl = bcast2(wlf);
                    ffma2(aU[j], wu, s1); ffma2(aU[j], wl, s2);
                    ffma2(aV[j], wu, s3); ffma2(aV[j], wl, s4);
                }
            }
        }
        __syncthreads();
        float4* ub = reinterpret_cast<float4*>(smem_raw);   // [64k][32 pairs]
        #pragma unroll
        for (int p = 0; p < 2; ++p) {
            if (hs == p) {
                #pragma unroll
                for (int j = 0; j < 4; ++j) {
                    float2 u = unpack2(aU[j]), v = unpack2(aV[j]);
                    int idx = (kb + j) * 32 + lane;
                    if (p == 0) ub[idx] = make_float4(u.x, v.x, u.y, v.y);
                    else {
                        float4 x = ub[idx];
                        x.x += u.x; x.y += v.x; x.z += u.y; x.w += v.y;
                        ub[idx] = x;
                    }
                }
            }
            __syncthreads();
        }
        float4* dst = reinterpret_cast<float4*>(&g_UV[k0][0][0]);
        atomicAdd(&dst[t],        ub[t]);
        atomicAdd(&dst[t + 1024], ub[t + 1024]);
    }
    grid_sync();

    // ============= P3: mm2  LV8[hsplit][b][k] = partial over this h-range ===
    if (B < 128) {
        int kblk = B >> 3, hsplit = B & 7;         // 16 kblk x 32k, 8 hsplit x 64h
        int k0 = kblk * 32, hb = hsplit * 64;
        ull*   uP  = reinterpret_cast<ull*>(smem_raw);             // [64h][32bp]
        ull*   vP  = reinterpret_cast<ull*>(smem_raw + 16384);     // [64h][32bp]
        float* swt = reinterpret_cast<float*>(smem_raw + 32768);   // [2m][32k][64h]
        #pragma unroll
        for (int i = t; i < 2048; i += 1024) {
            int h = i >> 5, bp = i & 31;
            float4 q = __ldcg(reinterpret_cast<const float4*>(&g_UV[hb + h][bp * 2][0]));
            uP[h * 32 + bp] = pack2(q.x, q.z);     // (U_b0, U_b1)
            vP[h * 32 + bp] = pack2(q.y, q.w);     // (V_b0, V_b1)
        }
        {
            int m = t >> 9, r = (t >> 4) & 31, i4 = t & 15;
            const float* W = m ? wsl : wsu;
            float4 v = ldg_el128(&W[(size_t)(k0 + r) * HH + hb + i4 * 4], POL);
            *reinterpret_cast<float4*>(&swt[(m * 32 + r) * 64 + i4 * 4]) = v;
        }
        __syncthreads();
        int w = t >> 5, lane = t & 31;
        int kg = w & 7, hs = w >> 3;               // 8 kgroups x 4k, 4 hsubs x 16h
        int kb = kg * 4;
        ull acc[4] = {0, 0, 0, 0};                 // packed (b0, b0+1)
        #pragma unroll 1
        for (int hq = 0; hq < 8; ++hq) {           // 2 h per iteration
            int h = hs * 16 + hq * 2;
            ull wu2[4], wl2[4];
            #pragma unroll
            for (int j = 0; j < 4; ++j) {
                wu2[j] = *reinterpret_cast<const ull*>(&swt[(kb + j) * 64 + h]);
                wl2[j] = *reinterpret_cast<const ull*>(&swt[(32 + kb + j) * 64 + h]);
            }
            #pragma unroll
            for (int d = 0; d < 2; ++d) {
                ull up = uP[(h + d) * 32 + lane];
                ull vp = vP[(h + d) * 32 + lane];
                #pragma unroll
                for (int j = 0; j < 4; ++j) {
                    float2 qu = unpack2(wu2[j]), ql = unpack2(wl2[j]);
                    float wuf = d ? qu.y : qu.x;
                    float wlf = d ? ql.y : ql.x;
                    ffma2(acc[j], bcast2(wuf), up);
                    ffma2(acc[j], bcast2(wlf), vp);
                }
            }
        }
        __syncthreads();
        float* lv = reinterpret_cast<float*>(smem_raw);   // [32k][64b]
        #pragma unroll
        for (int p = 0; p < 4; ++p) {
            if (hs == p) {
                #pragma unroll
                for (int j = 0; j < 4; ++j) {
                    float2 u = unpack2(acc[j]);
                    int r0 = (kb + j) * 64 + 2 * lane;
                    if (p == 0) { lv[r0] = u.x; lv[r0 + 1] = u.y; }
                    else        { lv[r0] += u.x; lv[r0 + 1] += u.y; }
                }
            }
            __syncthreads();
        }
        // plain per-hsplit stores — every (hsplit, b, k) written unconditionally
        int b = t & 63, k = (t >> 6) * 2;
        float2 v = make_float2(lv[k * 64 + b], lv[(k + 1) * 64 + b]);
        *reinterpret_cast<float2*>(&g_LV8[hsplit][b][k0 + k]) = v;
    }
    grid_sync();

    // ============= P4: softmax over sum of 8 LV partials ====================
    if (B < 64) {
        float* red = reinterpret_cast<float*>(smem_raw);
        int warp = t >> 5, lane = t & 31;
        float x = -1e30f;
        if (t < 512) {
            float s = __ldcg(&g_LV8[0][B][t]) + __ldcg(&g_LV8[1][B][t])
                    + __ldcg(&g_LV8[2][B][t]) + __ldcg(&g_LV8[3][B][t])
                    + __ldcg(&g_LV8[4][B][t]) + __ldcg(&g_LV8[5][B][t])
                    + __ldcg(&g_LV8[6][B][t]) + __ldcg(&g_LV8[7][B][t]);
            x = s + __ldcg(&g_usr[t]);
        }
        float m = x;
        #pragma unroll
        for (int o = 16; o; o >>= 1) m = fmaxf(m, __shfl_xor_sync(0xffffffffu, m, o));
        if (lane == 0) red[warp] = m;
        __syncthreads();
        if (t == 0) {
            float M = red[0];
            #pragma unroll
            for (int i = 1; i < 32; ++i) M = fmaxf(M, red[i]);
            red[32] = M;
        }
        __syncthreads();
        float M = red[32];
        float e = (t < 512) ? expf(x - M) : 0.f;
        float s = e;
        #pragma unroll
        for (int o = 16; o; o >>= 1) s += __shfl_xor_sync(0xffffffffu, s, o);
        __syncthreads();
        if (lane == 0) red[warp] = s;
        __syncthreads();
        if (t == 0) {
            float S = 0.f;
            #pragma unroll
            for (int i = 0; i < 32; ++i) S += red[i];
            red[33] = S;
        }
        __syncthreads();
        if (t < 512) out[B * HH + t] = e * (1.f / red[33]);
    } else {
        // restore g_UV == 0 invariant
        int idx = (B - 64) * 1024 + t;
        if (idx < 16384)
            reinterpret_cast<float4*>(g_UV)[idx] = make_float4(0.f, 0.f, 0.f, 0.f);
    }
}

// ---------------------------------------------------------------------------
extern "C" void kernel_launch(void* const* d_in, const int* in_sizes, int n_in,
                              void* d_out, int out_size) {
    const float* tdu  = (const float*)d_in[0];
    const float* tdl  = (const float*)d_in[1];
    const float* ldu  = (const float*)d_in[2];
    const float* ldl  = (const float*)d_in[3];
    const int*   cur  = (const int*)  d_in[4];
    const int*   llen = (const int*)  d_in[5];
    const float* wih  = (const float*)d_in[6];
    const float* wtu  = (const float*)d_in[7];
    const float* wtl  = (const float*)d_in[8];
    const float* wsu  = (const float*)d_in[9];
    const float* wsl  = (const float*)d_in[10];
    const float* h0   = (const float*)d_in[11];
    const float* locw = (const float*)d_in[12];
    float* out = (float*)d_out;

    k_fused<<<NBLK, 1024>>>(tdu, tdl, ldu, ldl, cur, llen,
                            wih, wtu, wtl, wsu, wsl, h0, locw, out);
}

// round 16
// speedup vs baseline: 1.4469x; 1.1820x over previous
#include <cuda_runtime.h>

#define BB 64
#define LL 512
#define HH 512

typedef unsigned long long ull;

// Scratch (device globals). g_S4 / g_LV8 fully overwritten every launch.
// g_UV: zero-at-exit invariant (k2 accumulates, k4 re-zeroes).
__device__ __align__(16) float g_S4[8][HH][BB][4]; // per-split packed sums
__device__ __align__(16) float g_UV[HH][BB][2];    // packed {U,V}
__device__ __align__(16) float g_LV8[8][BB][HH];   // per-hsplit loc_vec partials
__device__ __align__(16) float g_usr[HH];

// ---- packed fp32x2 helpers -------------------------------------------------
__device__ __forceinline__ ull pack2(float x, float y) {
    ull r; asm("mov.b64 %0, {%1, %2};" : "=l"(r) : "f"(x), "f"(y)); return r;
}
__device__ __forceinline__ ull bcast2(float x) { return pack2(x, x); }
__device__ __forceinline__ float2 unpack2(ull v) {
    float2 r; asm("mov.b64 {%0, %1}, %2;" : "=f"(r.x), "=f"(r.y) : "l"(v)); return r;
}
__device__ __forceinline__ void ffma2(ull& d, ull a, ull b) {
    asm("fma.rn.f32x2 %0, %1, %2, %0;" : "+l"(d) : "l"(a), "l"(b));
}

// ============================================================================
// k1: gather. Blocks [0,512): one (b, split) unit each, 256 threads,
// thread owns an h-pair. Blocks [512,544): usr_vec = Wih @ h0.
// ============================================================================
__global__ void __launch_bounds__(256) k1_gather(
        const float* __restrict__ tdu, const float* __restrict__ tdl,
        const float* __restrict__ ldu, const float* __restrict__ ldl,
        const int*   __restrict__ cur, const int* __restrict__ llen,
        const float* __restrict__ wih, const float* __restrict__ h0,
        const float* __restrict__ locw) {
    const int B = blockIdx.x;
    const int t = threadIdx.x;

    if (B >= 512) {      // usr_vec: 32 blocks x 16 k, 16 lanes per k
        int k    = (B - 512) * 16 + (t >> 4);
        int lane = t & 15;
        float s = 0.f;
        #pragma unroll 8
        for (int h = lane; h < HH; h += 16)
            s += wih[(size_t)k * HH + h] * __ldg(&h0[h]);
        #pragma unroll
        for (int o = 8; o; o >>= 1) s += __shfl_down_sync(0xffffffffu, s, o, 16);
        if (lane == 0) g_usr[k] = s;
        return;
    }

    __shared__ __align__(16) float4 s_cf[64];
    __shared__ int s_idx[64];

    int b = B & 63, sp = B >> 6;       // 8 splits
    int len = __ldg(&llen[b]);
    int cnt = (len > sp) ? ((len - sp + 7) >> 3) : 0;

    if (t < 64) {
        int l = sp + 8 * t;
        if (l < len) {
            int o = b * LL + l;
            float tu = tdu[o], tl = tdl[o];
            float lu = ldu[o], ll = ldl[o];
            float tden = 1.f / (tu + tl + 1e-9f);
            float lden = 1.f / (lu + ll + 1e-9f);
            float a = tu * tden, bb_ = tl * tden;
            float c = lu * lden, dd  = ll * lden;
            s_cf[t]  = make_float4(c * a, c * bb_, dd * a, dd * bb_);
            s_idx[t] = cur[o];
        }
    }
    __syncthreads();

    const float* base = locw + 2 * t;      // h-pair (2t, 2t+1)

    ull a1 = 0, a2 = 0, a3 = 0, a4 = 0;    // packed (h_even, h_odd)
    int r = 0;
    for (; r + 4 <= cnt; r += 4) {
        ull v0 = __ldg(reinterpret_cast<const ull*>(base + (size_t)s_idx[r]     * HH));
        ull v1 = __ldg(reinterpret_cast<const ull*>(base + (size_t)s_idx[r + 1] * HH));
        ull v2 = __ldg(reinterpret_cast<const ull*>(base + (size_t)s_idx[r + 2] * HH));
        ull v3 = __ldg(reinterpret_cast<const ull*>(base + (size_t)s_idx[r + 3] * HH));
        float4 c0 = s_cf[r], c1 = s_cf[r + 1], c2 = s_cf[r + 2], c3 = s_cf[r + 3];
        ffma2(a1, bcast2(c0.x), v0); ffma2(a2, bcast2(c0.y), v0);
        ffma2(a3, bcast2(c0.z), v0); ffma2(a4, bcast2(c0.w), v0);
        ffma2(a1, bcast2(c1.x), v1); ffma2(a2, bcast2(c1.y), v1);
        ffma2(a3, bcast2(c1.z), v1); ffma2(a4, bcast2(c1.w), v1);
        ffma2(a1, bcast2(c2.x), v2); ffma2(a2, bcast2(c2.y), v2);
        ffma2(a3, bcast2(c2.z), v2); ffma2(a4, bcast2(c2.w), v2);
        ffma2(a1, bcast2(c3.x), v3); ffma2(a2, bcast2(c3.y), v3);
        ffma2(a3, bcast2(c3.z), v3); ffma2(a4, bcast2(c3.w), v3);
    }
    for (; r < cnt; ++r) {
        ull v = __ldg(reinterpret_cast<const ull*>(base + (size_t)s_idx[r] * HH));
        float4 cf = s_cf[r];
        ffma2(a1, bcast2(cf.x), v); ffma2(a2, bcast2(cf.y), v);
        ffma2(a3, bcast2(cf.z), v); ffma2(a4, bcast2(cf.w), v);
    }
    // unconditional plain stores (zeros when cnt==0)
    float2 e1 = unpack2(a1), e2 = unpack2(a2), e3 = unpack2(a3), e4 = unpack2(a4);
    *reinterpret_cast<float4*>(&g_S4[sp][2 * t][b][0]) =
        make_float4(e1.x, e2.x, e3.x, e4.x);
    *reinterpret_cast<float4*>(&g_S4[sp][2 * t + 1][b][0]) =
        make_float4(e1.y, e2.y, e3.y, e4.y);
}

// ============================================================================
// k2: mm1. Grid 128 = 4 kblk (128 k) x 32 hsplit (16 h). 256 threads, 8 warps.
// Warp owns 16 k, all 16 h; lane owns a b-pair. REDs into g_UV.
// ============================================================================
__global__ void __launch_bounds__(256) k2_mm1(
        const float* __restrict__ wtu, const float* __restrict__ wtl) {
    __shared__ __align__(16) float s_t[16 * 256];      // [16h][4s][64b]
    __shared__ __align__(16) float swt[2 * 128 * 16];  // [2m][128k][16h]
    const int B = blockIdx.x;
    const int t = threadIdx.x;
    int k0 = (B >> 5) * 128, hb = (B & 31) * 16;

    // stage S (sum of 8 split copies): 1024 (h,b) elements
    #pragma unroll
    for (int i = t; i < 1024; i += 256) {
        int h = i >> 6, b = i & 63;
        float4 a0 = __ldcg(reinterpret_cast<const float4*>(&g_S4[0][hb + h][b][0]));
        float4 a1 = __ldcg(reinterpret_cast<const float4*>(&g_S4[1][hb + h][b][0]));
        float4 a2 = __ldcg(reinterpret_cast<const float4*>(&g_S4[2][hb + h][b][0]));
        float4 a3 = __ldcg(reinterpret_cast<const float4*>(&g_S4[3][hb + h][b][0]));
        float4 a4 = __ldcg(reinterpret_cast<const float4*>(&g_S4[4][hb + h][b][0]));
        float4 a5 = __ldcg(reinterpret_cast<const float4*>(&g_S4[5][hb + h][b][0]));
        float4 a6 = __ldcg(reinterpret_cast<const float4*>(&g_S4[6][hb + h][b][0]));
        float4 a7 = __ldcg(reinterpret_cast<const float4*>(&g_S4[7][hb + h][b][0]));
        float sx = a0.x + a1.x + a2.x + a3.x + a4.x + a5.x + a6.x + a7.x;
        float sy = a0.y + a1.y + a2.y + a3.y + a4.y + a5.y + a6.y + a7.y;
        float sz = a0.z + a1.z + a2.z + a3.z + a4.z + a5.z + a6.z + a7.z;
        float sw = a0.w + a1.w + a2.w + a3.w + a4.w + a5.w + a6.w + a7.w;
        float* p = &s_t[h * 256 + b];
        p[0] = sx; p[64] = sy; p[128] = sz; p[192] = sw;
    }
    // stage weights: 2 mats x 128 k x 16 h = 1024 float4
    #pragma unroll
    for (int i = t; i < 1024; i += 256) {
        int m = i >> 9, rem = i & 511, r = rem >> 2, i4 = rem & 3;
        const float* W = m ? wtl : wtu;
        float4 v = __ldg(reinterpret_cast<const float4*>(
                       &W[(size_t)(k0 + r) * HH + hb + i4 * 4]));
        *reinterpret_cast<float4*>(&swt[(m * 128 + r) * 16 + i4 * 4]) = v;
    }
    __syncthreads();

    int w = t >> 5, lane = t & 31;
    int kb = w * 16;
    ull aU[16], aV[16];
    #pragma unroll
    for (int j = 0; j < 16; ++j) { aU[j] = 0; aV[j] = 0; }

    #pragma unroll 1
    for (int hp = 0; hp < 8; ++hp) {       // 2 h per iteration
        int h = hp * 2;
        const float* r0 = &s_t[h * 256];
        const float* r1 = &s_t[(h + 1) * 256];
        ull s1a = *reinterpret_cast<const ull*>(&r0[2 * lane]);
        ull s2a = *reinterpret_cast<const ull*>(&r0[64 + 2 * lane]);
        ull s3a = *reinterpret_cast<const ull*>(&r0[128 + 2 * lane]);
        ull s4a = *reinterpret_cast<const ull*>(&r0[192 + 2 * lane]);
        ull s1b = *reinterpret_cast<const ull*>(&r1[2 * lane]);
        ull s2b = *reinterpret_cast<const ull*>(&r1[64 + 2 * lane]);
        ull s3b = *reinterpret_cast<const ull*>(&r1[128 + 2 * lane]);
        ull s4b = *reinterpret_cast<const ull*>(&r1[192 + 2 * lane]);
        #pragma unroll
        for (int j = 0; j < 16; ++j) {
            ull wu2 = *reinterpret_cast<const ull*>(&swt[(kb + j) * 16 + h]);
            ull wl2 = *reinterpret_cast<const ull*>(&swt[(128 + kb + j) * 16 + h]);
            float2 qu = unpack2(wu2), ql = unpack2(wl2);
            ffma2(aU[j], bcast2(qu.x), s1a); ffma2(aU[j], bcast2(ql.x), s2a);
            ffma2(aV[j], bcast2(qu.x), s3a); ffma2(aV[j], bcast2(ql.x), s4a);
            ffma2(aU[j], bcast2(qu.y), s1b); ffma2(aU[j], bcast2(ql.y), s2b);
            ffma2(aV[j], bcast2(qu.y), s3b); ffma2(aV[j], bcast2(ql.y), s4b);
        }
    }
    // direct REDs (warps own disjoint k — no block reduction needed)
    #pragma unroll
    for (int j = 0; j < 16; ++j) {
        float2 u = unpack2(aU[j]), v = unpack2(aV[j]);
        atomicAdd(reinterpret_cast<float4*>(&g_UV[k0 + kb + j][2 * lane][0]),
                  make_float4(u.x, v.x, u.y, v.y));
    }
}

// ============================================================================
// k3: mm2. Grid 128 = 16 kblk (32 k) x 8 hsplit (64 h). 256 threads, 8 warps.
// Warp owns 4 k, all 64 h. Plain stores into g_LV8[hsplit].
// ============================================================================
__global__ void __launch_bounds__(256) k3_mm2(
        const float* __restrict__ wsu, const float* __restrict__ wsl) {
    __shared__ __align__(16) ull uP[64 * 32];          // [64h][32bp]
    __shared__ __align__(16) ull vP[64 * 32];
    __shared__ __align__(16) float swt[2 * 32 * 64];   // [2m][32k][64h]
    const int B = blockIdx.x;
    const int t = threadIdx.x;
    int k0 = (B >> 3) * 32, hb = (B & 7) * 64, hsplit = B & 7;

    #pragma unroll
    for (int i = t; i < 2048; i += 256) {
        int h = i >> 5, bp = i & 31;
        float4 q = __ldcg(reinterpret_cast<const float4*>(&g_UV[hb + h][bp * 2][0]));
        uP[h * 32 + bp] = pack2(q.x, q.z);     // (U_b0, U_b1)
        vP[h * 32 + bp] = pack2(q.y, q.w);     // (V_b0, V_b1)
    }
    #pragma unroll
    for (int i = t; i < 1024; i += 256) {
        int m = i >> 9, rem = i & 511, r = rem >> 4, i4 = rem & 15;
        const float* W = m ? wsl : wsu;
        float4 v = __ldg(reinterpret_cast<const float4*>(
                       &W[(size_t)(k0 + r) * HH + hb + i4 * 4]));
        *reinterpret_cast<float4*>(&swt[(m * 32 + r) * 64 + i4 * 4]) = v;
    }
    __syncthreads();

    int w = t >> 5, lane = t & 31;
    int kb = w * 4;
    ull acc[4] = {0, 0, 0, 0};
    #pragma unroll 1
    for (int hp = 0; hp < 32; ++hp) {      // 2 h per iteration
        int h = hp * 2;
        ull ua = uP[h * 32 + lane],       va = vP[h * 32 + lane];
        ull ub = uP[(h + 1) * 32 + lane], vb = vP[(h + 1) * 32 + lane];
        #pragma unroll
        for (int j = 0; j < 4; ++j) {
            ull wu2 = *reinterpret_cast<const ull*>(&swt[(kb + j) * 64 + h]);
            ull wl2 = *reinterpret_cast<const ull*>(&swt[(32 + kb + j) * 64 + h]);
            float2 qu = unpack2(wu2), ql = unpack2(wl2);
            ffma2(acc[j], bcast2(qu.x), ua); ffma2(acc[j], bcast2(ql.x), va);
            ffma2(acc[j], bcast2(qu.y), ub); ffma2(acc[j], bcast2(ql.y), vb);
        }
    }
    float2 q0 = unpack2(acc[0]), q1 = unpack2(acc[1]),
           q2 = unpack2(acc[2]), q3 = unpack2(acc[3]);
    int b0 = 2 * lane;
    *reinterpret_cast<float4*>(&g_LV8[hsplit][b0][k0 + kb]) =
        make_float4(q0.x, q1.x, q2.x, q3.x);
    *reinterpret_cast<float4*>(&g_LV8[hsplit][b0 + 1][k0 + kb]) =
        make_float4(q0.y, q1.y, q2.y, q3.y);
}

// ============================================================================
// k4: softmax over sum of 8 LV partials (blocks [0,64)), plus g_UV re-zero
// (blocks [64,80)) to restore the zero-at-exit invariant for the next replay.
// ============================================================================
__global__ void __launch_bounds__(512) k4_softmax(float* __restrict__ out) {
    const int B = blockIdx.x;
    const int t = threadIdx.x;

    if (B >= 64) {
        int idx = (B - 64) * 512 + t;      // 8192 threads, 16384 float4
        float4 z = make_float4(0.f, 0.f, 0.f, 0.f);
        reinterpret_cast<float4*>(g_UV)[idx] = z;
        reinterpret_cast<float4*>(g_UV)[idx + 8192] = z;
        return;
    }

    __shared__ float red[18];
    int warp = t >> 5, lane = t & 31;
    float x = __ldcg(&g_LV8[0][B][t]) + __ldcg(&g_LV8[1][B][t])
            + __ldcg(&g_LV8[2][B][t]) + __ldcg(&g_LV8[3][B][t])
            + __ldcg(&g_LV8[4][B][t]) + __ldcg(&g_LV8[5][B][t])
            + __ldcg(&g_LV8[6][B][t]) + __ldcg(&g_LV8[7][B][t])
            + __ldg(&g_usr[t]);

    float m = x;
    #pragma unroll
    for (int o = 16; o; o >>= 1) m = fmaxf(m, __shfl_xor_sync(0xffffffffu, m, o));
    if (lane == 0) red[warp] = m;
    __syncthreads();
    if (t == 0) {
        float M = red[0];
        #pragma unroll
        for (int i = 1; i < 16; ++i) M = fmaxf(M, red[i]);
        red[16] = M;
    }
    __syncthreads();
    float M = red[16];
    float e = expf(x - M);
    float s = e;
    #pragma unroll
    for (int o = 16; o; o >>= 1) s += __shfl_xor_sync(0xffffffffu, s, o);
    __syncthreads();
    if (lane == 0) red[warp] = s;
    __syncthreads();
    if (t == 0) {
        float S = 0.f;
        #pragma unroll
        for (int i = 0; i < 16; ++i) S += red[i];
        red[17] = S;
    }
    __syncthreads();
    out[B * HH + t] = e * (1.f / red[17]);
}

// ---------------------------------------------------------------------------
extern "C" void kernel_launch(void* const* d_in, const int* in_sizes, int n_in,
                              void* d_out, int out_size) {
    const float* tdu  = (const float*)d_in[0];
    const float* tdl  = (const float*)d_in[1];
    const float* ldu  = (const float*)d_in[2];
    const float* ldl  = (const float*)d_in[3];
    const int*   cur  = (const int*)  d_in[4];
    const int*   llen = (const int*)  d_in[5];
    const float* wih  = (const float*)d_in[6];
    const float* wtu  = (const float*)d_in[7];
    const float* wtl  = (const float*)d_in[8];
    const float* wsu  = (const float*)d_in[9];
    const float* wsl  = (const float*)d_in[10];
    const float* h0   = (const float*)d_in[11];
    const float* locw = (const float*)d_in[12];
    float* out = (float*)d_out;

    k1_gather<<<544, 256>>>(tdu, tdl, ldu, ldl, cur, llen, wih, h0, locw);
    k2_mm1<<<128, 256>>>(wtu, wtl);
    k3_mm2<<<128, 256>>>(wsu, wsl);
    k4_softmax<<<80, 512>>>(out);
}